// round 1
// baseline (speedup 1.0000x reference)
#include <cuda_runtime.h>
#include <stdint.h>

// C[M,N] = act( A[M,K] @ (W[N,K] * mask)^T + bias[N] )
// Tiling: BM=128, BN=64, BK=16, 256 threads, 8x4 micro-tile per thread.
#define BM 128
#define BN 64
#define BK 16

__global__ __launch_bounds__(256)
void sparse_linear_kernel(const float* __restrict__ A,       // [M,K]
                          const float* __restrict__ W,       // [N,K]
                          const uint32_t* __restrict__ Msk,  // [N,K], nonzero = keep (works for f32 or i32 bool)
                          const float* __restrict__ bias,    // [N]
                          float* __restrict__ C,             // [M,N]
                          float* __restrict__ C2,            // optional duplicate output (may be null)
                          int M, int N, int K, int doRelu)
{
    __shared__ float As[BK][BM + 1];   // +1 pad: conflict-free transposed stores
    __shared__ float Bs[BK][BN + 1];

    const int tid = threadIdx.x;
    const int tx  = tid & 15;          // 0..15 -> n direction (x4)
    const int ty  = tid >> 4;          // 0..15 -> m direction (x8)
    const int m0  = blockIdx.y * BM;   // M = 32768, always multiple of BM
    const int n0  = blockIdx.x * BN;

    float acc[8][4];
    #pragma unroll
    for (int i = 0; i < 8; i++)
        #pragma unroll
        for (int j = 0; j < 4; j++) acc[i][j] = 0.0f;

    for (int kb = 0; kb < K; kb += BK) {
        // ---- load A tile: 128x16 = 2048 elems, 8 per thread, k-contiguous (coalesced) ----
        #pragma unroll
        for (int i = 0; i < 8; i++) {
            int idx = tid + i * 256;
            int r = idx >> 4;          // row within tile 0..127
            int c = idx & 15;          // k within tile
            int gk = kb + c;
            float v = 0.0f;
            if (gk < K) v = A[(size_t)(m0 + r) * K + gk];
            As[c][r] = v;
        }
        // ---- load W tile with mask fused: 64x16 = 1024 elems, 4 per thread ----
        #pragma unroll
        for (int i = 0; i < 4; i++) {
            int idx = tid + i * 256;
            int r = idx >> 4;          // n within tile 0..63
            int c = idx & 15;          // k within tile
            int gk = kb + c;
            int gn = n0 + r;
            float v = 0.0f;
            if (gn < N && gk < K) {
                size_t off = (size_t)gn * K + gk;
                if (Msk[off] != 0u) v = W[off];
            }
            Bs[c][r] = v;
        }
        __syncthreads();

        #pragma unroll
        for (int kk = 0; kk < BK; kk++) {
            float a[8], b[4];
            #pragma unroll
            for (int i = 0; i < 8; i++) a[i] = As[kk][ty * 8 + i];
            #pragma unroll
            for (int j = 0; j < 4; j++) b[j] = Bs[kk][tx * 4 + j];
            #pragma unroll
            for (int i = 0; i < 8; i++)
                #pragma unroll
                for (int j = 0; j < 4; j++)
                    acc[i][j] = fmaf(a[i], b[j], acc[i][j]);
        }
        __syncthreads();
    }

    // ---- epilogue: bias + optional relu, direct store into d_out slice(s) ----
    #pragma unroll
    for (int i = 0; i < 8; i++) {
        int gm = m0 + ty * 8 + i;
        #pragma unroll
        for (int j = 0; j < 4; j++) {
            int gn = n0 + tx * 4 + j;
            if (gn < N) {
                float v = acc[i][j] + bias[gn];
                if (doRelu) v = fmaxf(v, 0.0f);
                C[(size_t)gm * N + gn] = v;
                if (C2) C2[(size_t)gm * N + gn] = v;
            }
        }
    }
}

extern "C" void kernel_launch(void* const* d_in, const int* in_sizes, int n_in,
                              void* d_out, int out_size)
{
    (void)in_sizes; (void)n_in; (void)out_size;
    const int B = 32768;

    const float*    x  = (const float*)d_in[0];
    const float*    W1 = (const float*)d_in[1];
    const float*    b1 = (const float*)d_in[2];
    const uint32_t* m1 = (const uint32_t*)d_in[3];
    const float*    W2 = (const float*)d_in[4];
    const float*    b2 = (const float*)d_in[5];
    const uint32_t* m2 = (const uint32_t*)d_in[6];
    const float*    W3 = (const float*)d_in[7];
    const float*    b3 = (const float*)d_in[8];
    const uint32_t* m3 = (const uint32_t*)d_in[9];
    const float*    W4 = (const float*)d_in[10];
    const float*    b4 = (const float*)d_in[11];
    const uint32_t* m4 = (const uint32_t*)d_in[12];
    const float*    W5 = (const float*)d_in[13];
    const float*    b5 = (const float*)d_in[14];
    const uint32_t* m5 = (const uint32_t*)d_in[15];

    float* out = (float*)d_out;
    // Output tuple layout: (h5, h1, h2, h3, h4, h5)
    float* h5a = out;                                   // [B,6]
    float* h1  = out + (size_t)B * 6;                   // [B,1000]
    float* h2  = h1  + (size_t)B * 1000;                // [B,800]
    float* h3  = h2  + (size_t)B * 800;                 // [B,400]
    float* h4  = h3  + (size_t)B * 400;                 // [B,600]
    float* h5b = h4  + (size_t)B * 600;                 // [B,6]

    dim3 block(256);
    dim3 gridM(1, B / BM);

    // L1: [B,1024] -> [B,1000], relu
    { dim3 g((1000 + BN - 1) / BN, B / BM);
      sparse_linear_kernel<<<g, block>>>(x,  W1, m1, b1, h1,  nullptr, B, 1000, 1024, 1); }
    // L2: [B,1000] -> [B,800], relu
    { dim3 g((800 + BN - 1) / BN, B / BM);
      sparse_linear_kernel<<<g, block>>>(h1, W2, m2, b2, h2,  nullptr, B, 800, 1000, 1); }
    // L3: [B,800] -> [B,400], relu
    { dim3 g((400 + BN - 1) / BN, B / BM);
      sparse_linear_kernel<<<g, block>>>(h2, W3, m3, b3, h3,  nullptr, B, 400, 800, 1); }
    // L4: [B,400] -> [B,600], no relu
    { dim3 g((600 + BN - 1) / BN, B / BM);
      sparse_linear_kernel<<<g, block>>>(h3, W4, m4, b4, h4,  nullptr, B, 600, 400, 0); }
    // L5: [B,600] -> [B,6], no relu, write both h5 slots
    { dim3 g(1, B / BM);
      sparse_linear_kernel<<<g, block>>>(h4, W5, m5, b5, h5a, h5b,     B, 6, 600, 0); }
}

// round 2
// speedup vs baseline: 4.7742x; 4.7742x over previous
#include <cuda_runtime.h>
#include <stdint.h>

// ---------------------------------------------------------------------------
// C[M,N] = act( A[M,K] @ (W[N,K]*mask)^T + bias[N] )  via tf32 mma.sync
// BM=128, BN=64, BK=32, 256 threads (8 warps, 4x2), warp tile 32x32.
// ---------------------------------------------------------------------------
#define BM 128
#define BN 64
#define BK 32
#define SPAD 4
#define SSTR (BK + SPAD)   // 36 floats per smem row -> conflict-free frag loads

__device__ __forceinline__ uint32_t f2tf32(float f) {
    uint32_t r;
    asm("cvt.rna.tf32.f32 %0, %1;" : "=r"(r) : "f"(f));
    return r;
}

__device__ __forceinline__ void mma_tf32(float* c,
                                         uint32_t a0, uint32_t a1, uint32_t a2, uint32_t a3,
                                         uint32_t b0, uint32_t b1) {
    asm volatile("mma.sync.aligned.m16n8k8.row.col.f32.tf32.tf32.f32 "
                 "{%0,%1,%2,%3}, {%4,%5,%6,%7}, {%8,%9}, {%0,%1,%2,%3};"
                 : "+f"(c[0]), "+f"(c[1]), "+f"(c[2]), "+f"(c[3])
                 : "r"(a0), "r"(a1), "r"(a2), "r"(a3), "r"(b0), "r"(b1));
}

__global__ __launch_bounds__(256)
void mma_layer_kernel(const float* __restrict__ A,       // [M,K]
                      const float* __restrict__ W,       // [N,K]
                      const uint32_t* __restrict__ Msk,  // [N,K] nonzero = keep
                      const float* __restrict__ bias,    // [N]
                      float* __restrict__ C,             // [M,N]
                      int M, int N, int K, int doRelu)
{
    __shared__ uint32_t As[BM][SSTR];
    __shared__ uint32_t Ws[BN][SSTR];

    const int tid  = threadIdx.x;
    const int warp = tid >> 5;
    const int lane = tid & 31;
    const int g    = lane >> 2;   // 0..7
    const int t    = lane & 3;    // 0..3
    const int wm0  = (warp & 3) * 32;
    const int wn0  = (warp >> 2) * 32;
    const int m0   = blockIdx.y * BM;   // M % 128 == 0 always
    const int n0   = blockIdx.x * BN;

    float acc[2][4][4];
    #pragma unroll
    for (int i = 0; i < 2; i++)
        #pragma unroll
        for (int j = 0; j < 4; j++)
            #pragma unroll
            for (int q = 0; q < 4; q++) acc[i][j][q] = 0.0f;

    const int lr = tid >> 3;        // 0..31 : row within a 32-row pass
    const int lc = (tid & 7) * 4;   // 0,4,...,28 : k offset (float4)

    for (int kb = 0; kb < K; kb += BK) {
        const int gk = kb + lc;     // K % 4 == 0 for all layers -> float4 safe
        // ---- A tile: 128x32, tf32-rounded into smem ----
        #pragma unroll
        for (int p = 0; p < 4; p++) {
            int r = p * 32 + lr;
            float4 v = make_float4(0.f, 0.f, 0.f, 0.f);
            if (gk < K) v = *(const float4*)&A[(size_t)(m0 + r) * K + gk];
            As[r][lc + 0] = f2tf32(v.x);
            As[r][lc + 1] = f2tf32(v.y);
            As[r][lc + 2] = f2tf32(v.z);
            As[r][lc + 3] = f2tf32(v.w);
        }
        // ---- W tile: 64x32, mask fused, tf32-rounded ----
        #pragma unroll
        for (int p = 0; p < 2; p++) {
            int r  = p * 32 + lr;
            int gn = n0 + r;
            float4 v = make_float4(0.f, 0.f, 0.f, 0.f);
            if (gn < N && gk < K) {
                size_t off = (size_t)gn * K + gk;
                v = *(const float4*)&W[off];
                uint4 mk = *(const uint4*)&Msk[off];
                if (!mk.x) v.x = 0.f;
                if (!mk.y) v.y = 0.f;
                if (!mk.z) v.z = 0.f;
                if (!mk.w) v.w = 0.f;
            }
            Ws[r][lc + 0] = f2tf32(v.x);
            Ws[r][lc + 1] = f2tf32(v.y);
            Ws[r][lc + 2] = f2tf32(v.z);
            Ws[r][lc + 3] = f2tf32(v.w);
        }
        __syncthreads();

        #pragma unroll
        for (int kk = 0; kk < BK / 8; kk++) {
            const int k0 = kk * 8;
            uint32_t a[2][4], b[4][2];
            #pragma unroll
            for (int mi = 0; mi < 2; mi++) {
                int rm = wm0 + mi * 16;
                a[mi][0] = As[rm + g    ][k0 + t    ];
                a[mi][1] = As[rm + 8 + g][k0 + t    ];
                a[mi][2] = As[rm + g    ][k0 + 4 + t];
                a[mi][3] = As[rm + 8 + g][k0 + 4 + t];
            }
            #pragma unroll
            for (int nj = 0; nj < 4; nj++) {
                int rn = wn0 + nj * 8 + g;
                b[nj][0] = Ws[rn][k0 + t    ];
                b[nj][1] = Ws[rn][k0 + 4 + t];
            }
            #pragma unroll
            for (int mi = 0; mi < 2; mi++)
                #pragma unroll
                for (int nj = 0; nj < 4; nj++)
                    mma_tf32(acc[mi][nj], a[mi][0], a[mi][1], a[mi][2], a[mi][3],
                             b[nj][0], b[nj][1]);
        }
        __syncthreads();
    }

    // ---- epilogue: bias + optional relu ----
    #pragma unroll
    for (int mi = 0; mi < 2; mi++) {
        int r0 = m0 + wm0 + mi * 16 + g;
        float* cr0 = &C[(size_t)r0 * N];
        float* cr1 = &C[(size_t)(r0 + 8) * N];
        #pragma unroll
        for (int nj = 0; nj < 4; nj++) {
            int cb = n0 + wn0 + nj * 8 + t * 2;
            if (cb < N) {
                float bv = bias[cb];
                float v0 = acc[mi][nj][0] + bv;
                float v2 = acc[mi][nj][2] + bv;
                if (doRelu) { v0 = fmaxf(v0, 0.f); v2 = fmaxf(v2, 0.f); }
                cr0[cb] = v0;
                cr1[cb] = v2;
            }
            if (cb + 1 < N) {
                float bv = bias[cb + 1];
                float v1 = acc[mi][nj][1] + bv;
                float v3 = acc[mi][nj][3] + bv;
                if (doRelu) { v1 = fmaxf(v1, 0.f); v3 = fmaxf(v3, 0.f); }
                cr0[cb + 1] = v1;
                cr1[cb + 1] = v3;
            }
        }
    }
}

// ---------------------------------------------------------------------------
// Layer 5: [B,600] -> [B,6], memory-bound GEMV. Warp per row, coalesced A
// reads, masked W5 staged in smem, shuffle reduction. Writes both h5 slots.
// ---------------------------------------------------------------------------
__global__ __launch_bounds__(256)
void final_layer_kernel(const float* __restrict__ A,       // [M,600]
                        const float* __restrict__ W,       // [6,600]
                        const uint32_t* __restrict__ Msk,  // [6,600]
                        const float* __restrict__ bias,    // [6]
                        float* __restrict__ O1, float* __restrict__ O2,
                        int K)                              // K=600
{
    __shared__ float ws[600 * 6];   // ws[k*6 + n]
    const int tid = threadIdx.x;
    for (int idx = tid; idx < K * 6; idx += 256) {
        int n = idx / K, k = idx % K;
        size_t off = (size_t)n * K + k;
        ws[k * 6 + n] = (Msk[off] != 0u) ? W[off] : 0.0f;
    }
    __syncthreads();

    const int warp = tid >> 5, lane = tid & 31;
    const int row  = blockIdx.x * 8 + warp;
    const float* a = &A[(size_t)row * K];

    float acc[6] = {0.f, 0.f, 0.f, 0.f, 0.f, 0.f};
    for (int k = lane; k < K; k += 32) {
        float av = a[k];
        #pragma unroll
        for (int j = 0; j < 6; j++) acc[j] = fmaf(av, ws[k * 6 + j], acc[j]);
    }
    #pragma unroll
    for (int j = 0; j < 6; j++) {
        #pragma unroll
        for (int o = 16; o > 0; o >>= 1)
            acc[j] += __shfl_xor_sync(0xffffffffu, acc[j], o);
    }
    if (lane == 0) {
        #pragma unroll
        for (int j = 0; j < 6; j++) {
            float v = acc[j] + bias[j];
            O1[(size_t)row * 6 + j] = v;
            O2[(size_t)row * 6 + j] = v;
        }
    }
}

extern "C" void kernel_launch(void* const* d_in, const int* in_sizes, int n_in,
                              void* d_out, int out_size)
{
    (void)in_sizes; (void)n_in; (void)out_size;
    const int B = 32768;

    const float*    x  = (const float*)d_in[0];
    const float*    W1 = (const float*)d_in[1];
    const float*    b1 = (const float*)d_in[2];
    const uint32_t* m1 = (const uint32_t*)d_in[3];
    const float*    W2 = (const float*)d_in[4];
    const float*    b2 = (const float*)d_in[5];
    const uint32_t* m2 = (const uint32_t*)d_in[6];
    const float*    W3 = (const float*)d_in[7];
    const float*    b3 = (const float*)d_in[8];
    const uint32_t* m3 = (const uint32_t*)d_in[9];
    const float*    W4 = (const float*)d_in[10];
    const float*    b4 = (const float*)d_in[11];
    const uint32_t* m4 = (const uint32_t*)d_in[12];
    const float*    W5 = (const float*)d_in[13];
    const float*    b5 = (const float*)d_in[14];
    const uint32_t* m5 = (const uint32_t*)d_in[15];

    float* out = (float*)d_out;
    // Output tuple layout: (h5, h1, h2, h3, h4, h5)
    float* h5a = out;                                   // [B,6]
    float* h1  = out + (size_t)B * 6;                   // [B,1000]
    float* h2  = h1  + (size_t)B * 1000;                // [B,800]
    float* h3  = h2  + (size_t)B * 800;                 // [B,400]
    float* h4  = h3  + (size_t)B * 400;                 // [B,600]
    float* h5b = h4  + (size_t)B * 600;                 // [B,6]

    dim3 block(256);

    { dim3 g((1000 + BN - 1) / BN, B / BM);
      mma_layer_kernel<<<g, block>>>(x,  W1, m1, b1, h1, B, 1000, 1024, 1); }
    { dim3 g((800 + BN - 1) / BN, B / BM);
      mma_layer_kernel<<<g, block>>>(h1, W2, m2, b2, h2, B, 800, 1000, 1); }
    { dim3 g((400 + BN - 1) / BN, B / BM);
      mma_layer_kernel<<<g, block>>>(h2, W3, m3, b3, h3, B, 400, 800, 1); }
    { dim3 g((600 + BN - 1) / BN, B / BM);
      mma_layer_kernel<<<g, block>>>(h3, W4, m4, b4, h4, B, 600, 400, 0); }
    { dim3 g(B / 8);
      final_layer_kernel<<<g, block>>>(h4, W5, m5, b5, h5a, h5b, 600); }
}

// round 3
// speedup vs baseline: 7.0910x; 1.4853x over previous
#include <cuda_runtime.h>
#include <stdint.h>

// ===========================================================================
// 5-layer masked-dense MLP, tf32 mma.sync, fragment-permuted packed operands.
// BM=128, BN=128, BK=32, 256 threads (8 warps, 2m x 4n), warp tile 64x32.
// A/W tiles are pre-packed in fragment order -> mainloop = cp.async + LDS.128.
// ===========================================================================

#define NTHREADS 256

// ---- device scratch (allowed: __device__ globals, no runtime alloc) -------
// A-pack ping-pong buffers: max 32768 x 1024 tf32 words each.
__device__ uint32_t g_Apack0[33554432];
__device__ uint32_t g_Apack1[33554432];
// W-pack, all 4 MMA layers concatenated:
// L1: 8 ntiles * 32 kt * 4096 = 1048576
// L2: 7 * 32 * 4096          =  917504
// L3: 4 * 25 * 4096          =  409600
// L4: 5 * 13 * 4096          =  266240
__device__ uint32_t g_Wpack[2641920];
#define WOFF1 0
#define WOFF2 1048576
#define WOFF3 1966080
#define WOFF4 2375680

// ---------------------------------------------------------------------------
__device__ __forceinline__ uint32_t f2tf32(float f) {
    uint32_t r;
    asm("cvt.rna.tf32.f32 %0, %1;" : "=r"(r) : "f"(f));
    return r;
}

__device__ __forceinline__ uint32_t smem_u32(const void* p) {
    uint32_t a;
    asm("{ .reg .u64 t; cvta.to.shared.u64 t, %1; cvt.u32.u64 %0, t; }" : "=r"(a) : "l"(p));
    return a;
}

__device__ __forceinline__ void cpa16(uint32_t saddr, const void* g) {
    asm volatile("cp.async.cg.shared.global [%0], [%1], 16;" :: "r"(saddr), "l"(g));
}
#define CPA_COMMIT() asm volatile("cp.async.commit_group;")
#define CPA_WAIT1()  asm volatile("cp.async.wait_group 1;")

__device__ __forceinline__ void mma_tf32(float* c,
                                         uint32_t a0, uint32_t a1, uint32_t a2, uint32_t a3,
                                         uint32_t b0, uint32_t b1) {
    asm volatile("mma.sync.aligned.m16n8k8.row.col.f32.tf32.tf32.f32 "
                 "{%0,%1,%2,%3}, {%4,%5,%6,%7}, {%8,%9}, {%0,%1,%2,%3};"
                 : "+f"(c[0]), "+f"(c[1]), "+f"(c[2]), "+f"(c[3])
                 : "r"(a0), "r"(a1), "r"(a2), "r"(a3), "r"(b0), "r"(b1));
}

// A-pack index: tile [frag8][kk4][lane32][p4], 4096 words per (mtile,ktile).
__device__ __forceinline__ size_t apack_idx(int r, int k, int T) {
    int m_tile = r >> 7, frag = (r & 127) >> 4, r16 = r & 15;
    int g = r16 & 7, half = r16 >> 3;
    int kb = k >> 5, kk = (k & 31) >> 3, t = k & 3, hi = (k & 7) >> 2;
    return ((size_t)(m_tile * T + kb) << 12) + frag * 512 + kk * 128 + (4 * g + t) * 4 + (half + 2 * hi);
}

// W-pack index: tile [nj16][kk4][lane32][p2], 4096 words per (ntile,ktile).
__device__ __forceinline__ size_t wpack_idx(int n, int k, int T) {
    int n_tile = n >> 7, nj = (n & 127) >> 3, g = n & 7;
    int kb = k >> 5, kk = (k & 31) >> 3, t = k & 3, hi = (k & 7) >> 2;
    return ((size_t)(n_tile * T + kb) << 12) + nj * 256 + kk * 64 + (4 * g + t) * 2 + hi;
}

// ---------------------------------------------------------------------------
// Prep: pack masked+tf32 weights. One thread per packed element (grid-stride).
// ---------------------------------------------------------------------------
__global__ void wpack_kernel(const float* __restrict__ W, const uint32_t* __restrict__ Msk,
                             uint32_t* __restrict__ out, int N, int K, int Kpad, int nTiles)
{
    int T = Kpad >> 5;
    size_t total = (size_t)nTiles * 128 * Kpad;
    for (size_t idx = (size_t)blockIdx.x * blockDim.x + threadIdx.x; idx < total;
         idx += (size_t)gridDim.x * blockDim.x) {
        int n = (int)(idx / Kpad);
        int k = (int)(idx % Kpad);
        uint32_t v = 0u;
        if (n < N && k < K) {
            size_t off = (size_t)n * K + k;
            if (Msk[off] != 0u) v = f2tf32(W[off]);
        }
        out[wpack_idx(n, k, T)] = v;
    }
}

// Prep: pack x [32768,1024] into g_Apack0. One float4 per thread.
__global__ void xpack_kernel(const float* __restrict__ X, uint32_t* __restrict__ out)
{
    const int K = 1024, T = 32;
    int idx = blockIdx.x * blockDim.x + threadIdx.x;   // r*(K/4)+kc
    int kc = idx & 255;
    int r  = idx >> 8;
    float4 v = *(const float4*)&X[(size_t)r * K + kc * 4];
    int k = kc * 4;
    int m_tile = r >> 7, frag = (r & 127) >> 4, r16 = r & 15;
    int g = r16 & 7, half = r16 >> 3;
    int kb = k >> 5, kk = (k & 31) >> 3, hi = (k & 7) >> 2;
    size_t base = ((size_t)(m_tile * T + kb) << 12) + frag * 512 + kk * 128 + g * 16 + (half + 2 * hi);
    out[base + 0]  = f2tf32(v.x);
    out[base + 4]  = f2tf32(v.y);
    out[base + 8]  = f2tf32(v.z);
    out[base + 12] = f2tf32(v.w);
}

// ---------------------------------------------------------------------------
// Main GEMM: C = act(Apack @ Wpack^T + bias); also emits tf32 pack of C.
// ---------------------------------------------------------------------------
__global__ __launch_bounds__(NTHREADS, 2)
void mma_layer_kernel(const uint32_t* __restrict__ Ap,   // packed A
                      const uint32_t* __restrict__ Wp,   // packed W
                      const float* __restrict__ bias,
                      float* __restrict__ C,             // [M,N] fp32 out
                      uint32_t* __restrict__ packOut,    // next-layer A pack (or null)
                      int N, int T, int Tn, int KpadNext, int doRelu)
{
    extern __shared__ uint32_t dynsmem[];
    const uint32_t sbase = smem_u32(dynsmem);

    const int tid    = threadIdx.x;
    const int warp   = tid >> 5;
    const int lane   = tid & 31;
    const int warp_n = warp & 3;
    const int warp_m = warp >> 2;
    const int g      = lane >> 2;
    const int t      = lane & 3;
    const int mtile  = blockIdx.y;
    const int ntile  = blockIdx.x;
    const int m0     = mtile << 7;
    const int n0     = ntile << 7;

    const uint32_t* aSrc = Ap + ((size_t)mtile * T << 12);
    const uint32_t* wSrc = Wp + ((size_t)ntile * T << 12);

    float acc[4][4][4];
    #pragma unroll
    for (int i = 0; i < 4; i++)
        #pragma unroll
        for (int j = 0; j < 4; j++)
            #pragma unroll
            for (int q = 0; q < 4; q++) acc[i][j][q] = 0.f;

    // --- cp.async issue of one k-tile into stage s ---
    auto issue = [&](int s, int kb) {
        uint32_t ab = sbase + s * 32768u;
        uint32_t wb = ab + 16384u;
        const uint32_t* a = aSrc + ((size_t)kb << 12);
        const uint32_t* w = wSrc + ((size_t)kb << 12);
        #pragma unroll
        for (int j = 0; j < 4; j++) {
            int o = tid + j * 256;
            cpa16(ab + o * 16u, a + o * 4);
            cpa16(wb + o * 16u, w + o * 4);
        }
        CPA_COMMIT();
    };

    issue(0, 0);
    if (T > 1) issue(1, 1);

    for (int kb = 0; kb < T; kb++) {
        CPA_WAIT1();
        __syncthreads();
        if (kb + 2 < T) issue((kb + 2) % 3, kb + 2);

        const int s = kb % 3;
        const uint32_t ab = sbase + s * 32768u;
        const uint32_t wb = ab + 16384u;

        #pragma unroll
        for (int kk = 0; kk < 4; kk++) {
            uint32_t a[4][4], b[4][2];
            #pragma unroll
            for (int mi = 0; mi < 4; mi++) {
                int frag = warp_m * 4 + mi;
                uint32_t addr = ab + ((frag * 4 + kk) * 32 + lane) * 16u;
                asm volatile("ld.shared.v4.u32 {%0,%1,%2,%3}, [%4];"
                             : "=r"(a[mi][0]), "=r"(a[mi][1]), "=r"(a[mi][2]), "=r"(a[mi][3])
                             : "r"(addr));
            }
            #pragma unroll
            for (int nj = 0; nj < 4; nj++) {
                int njg = warp_n * 4 + nj;
                uint32_t addr = wb + ((njg * 4 + kk) * 32 + lane) * 8u;
                asm volatile("ld.shared.v2.u32 {%0,%1}, [%2];"
                             : "=r"(b[nj][0]), "=r"(b[nj][1]) : "r"(addr));
            }
            #pragma unroll
            for (int mi = 0; mi < 4; mi++)
                #pragma unroll
                for (int nj = 0; nj < 4; nj++)
                    mma_tf32(acc[mi][nj], a[mi][0], a[mi][1], a[mi][2], a[mi][3],
                             b[nj][0], b[nj][1]);
        }
        __syncthreads();
    }

    // --- epilogue: bias + relu -> C, and tf32 pack -> next layer ---
    #pragma unroll
    for (int mi = 0; mi < 4; mi++) {
        int r0 = m0 + warp_m * 64 + mi * 16 + g;
        #pragma unroll
        for (int nj = 0; nj < 4; nj++) {
            int cb = n0 + warp_n * 32 + nj * 8 + t * 2;
            #pragma unroll
            for (int q = 0; q < 2; q++) {
                int c = cb + q;
                float v0 = acc[mi][nj][q];
                float v2 = acc[mi][nj][q + 2];
                if (c < N) {
                    float bv = bias[c];
                    v0 += bv; v2 += bv;
                    if (doRelu) { v0 = fmaxf(v0, 0.f); v2 = fmaxf(v2, 0.f); }
                    C[(size_t)r0 * N + c] = v0;
                    C[(size_t)(r0 + 8) * N + c] = v2;
                }
                if (packOut && c < KpadNext) {
                    uint32_t p0 = (c < N) ? f2tf32(v0) : 0u;
                    uint32_t p2 = (c < N) ? f2tf32(v2) : 0u;
                    packOut[apack_idx(r0,     c, Tn)] = p0;
                    packOut[apack_idx(r0 + 8, c, Tn)] = p2;
                }
            }
        }
    }
}

// ---------------------------------------------------------------------------
// Layer 5: [B,600] -> [B,6] GEMV, warp per row, writes both h5 slots.
// ---------------------------------------------------------------------------
__global__ __launch_bounds__(256)
void final_layer_kernel(const float* __restrict__ A, const float* __restrict__ W,
                        const uint32_t* __restrict__ Msk, const float* __restrict__ bias,
                        float* __restrict__ O1, float* __restrict__ O2, int K)
{
    __shared__ float ws[600 * 6];
    const int tid = threadIdx.x;
    for (int idx = tid; idx < K * 6; idx += 256) {
        int n = idx / K, k = idx % K;
        size_t off = (size_t)n * K + k;
        ws[k * 6 + n] = (Msk[off] != 0u) ? W[off] : 0.0f;
    }
    __syncthreads();

    const int warp = tid >> 5, lane = tid & 31;
    const int row  = blockIdx.x * 8 + warp;
    const float* a = &A[(size_t)row * K];

    float acc[6] = {0.f, 0.f, 0.f, 0.f, 0.f, 0.f};
    for (int k = lane; k < K; k += 32) {
        float av = a[k];
        #pragma unroll
        for (int j = 0; j < 6; j++) acc[j] = fmaf(av, ws[k * 6 + j], acc[j]);
    }
    #pragma unroll
    for (int j = 0; j < 6; j++)
        #pragma unroll
        for (int o = 16; o > 0; o >>= 1)
            acc[j] += __shfl_xor_sync(0xffffffffu, acc[j], o);
    if (lane == 0) {
        #pragma unroll
        for (int j = 0; j < 6; j++) {
            float v = acc[j] + bias[j];
            O1[(size_t)row * 6 + j] = v;
            O2[(size_t)row * 6 + j] = v;
        }
    }
}

// ---------------------------------------------------------------------------
extern "C" void kernel_launch(void* const* d_in, const int* in_sizes, int n_in,
                              void* d_out, int out_size)
{
    (void)in_sizes; (void)n_in; (void)out_size;
    const int B = 32768;

    const float*    x  = (const float*)d_in[0];
    const float*    W1 = (const float*)d_in[1];
    const float*    b1 = (const float*)d_in[2];
    const uint32_t* m1 = (const uint32_t*)d_in[3];
    const float*    W2 = (const float*)d_in[4];
    const float*    b2 = (const float*)d_in[5];
    const uint32_t* m2 = (const uint32_t*)d_in[6];
    const float*    W3 = (const float*)d_in[7];
    const float*    b3 = (const float*)d_in[8];
    const uint32_t* m3 = (const uint32_t*)d_in[9];
    const float*    W4 = (const float*)d_in[10];
    const float*    b4 = (const float*)d_in[11];
    const uint32_t* m4 = (const uint32_t*)d_in[12];
    const float*    W5 = (const float*)d_in[13];
    const float*    b5 = (const float*)d_in[14];
    const uint32_t* m5 = (const uint32_t*)d_in[15];

    float* out = (float*)d_out;
    float* h5a = out;                    // [B,6]
    float* h1  = out + (size_t)B * 6;    // [B,1000]
    float* h2  = h1  + (size_t)B * 1000; // [B,800]
    float* h3  = h2  + (size_t)B * 800;  // [B,400]
    float* h4  = h3  + (size_t)B * 400;  // [B,600]
    float* h5b = h4  + (size_t)B * 600;  // [B,6]

    uint32_t *ap0, *ap1, *wp;
    cudaGetSymbolAddress((void**)&ap0, g_Apack0);
    cudaGetSymbolAddress((void**)&ap1, g_Apack1);
    cudaGetSymbolAddress((void**)&wp,  g_Wpack);

    static bool attrDone = false;
    if (!attrDone) {
        cudaFuncSetAttribute(mma_layer_kernel, cudaFuncAttributeMaxDynamicSharedMemorySize, 98304);
        attrDone = true;
    }

    // ---- prep: pack weights + x ----
    wpack_kernel<<<512, 256>>>(W1, m1, wp + WOFF1, 1000, 1024, 1024, 8);
    wpack_kernel<<<512, 256>>>(W2, m2, wp + WOFF2,  800, 1000, 1024, 7);
    wpack_kernel<<<256, 256>>>(W3, m3, wp + WOFF3,  400,  800,  800, 4);
    wpack_kernel<<<256, 256>>>(W4, m4, wp + WOFF4,  600,  400,  416, 5);
    xpack_kernel<<<B, 256>>>(x, ap0);

    dim3 blk(NTHREADS);
    const int SM = 98304;
    // L1: K=1024 (T=32) -> h1 [B,1000], pack -> ap1 (Kpad 1024, Tn=32)
    mma_layer_kernel<<<dim3(8,  B/128), blk, SM>>>(ap0, wp + WOFF1, b1, h1, ap1, 1000, 32, 32, 1024, 1);
    // L2: K=1000->1024 (T=32) -> h2 [B,800], pack -> ap0 (Kpad 800, Tn=25)
    mma_layer_kernel<<<dim3(7,  B/128), blk, SM>>>(ap1, wp + WOFF2, b2, h2, ap0,  800, 32, 25,  800, 1);
    // L3: K=800 (T=25) -> h3 [B,400], pack -> ap1 (Kpad 416, Tn=13)
    mma_layer_kernel<<<dim3(4,  B/128), blk, SM>>>(ap0, wp + WOFF3, b3, h3, ap1,  400, 25, 13,  416, 1);
    // L4: K=400->416 (T=13) -> h4 [B,600], no pack, no relu
    mma_layer_kernel<<<dim3(5,  B/128), blk, SM>>>(ap1, wp + WOFF4, b4, h4, nullptr, 600, 13, 0, 0, 0);
    // L5 GEMV
    final_layer_kernel<<<B/8, 256>>>(h4, W5, m5, b5, h5a, h5b, 600);
}

// round 5
// speedup vs baseline: 13.2995x; 1.8755x over previous
#include <cuda_runtime.h>
#include <cuda_fp16.h>
#include <stdint.h>

// ===========================================================================
// 5-layer masked MLP, fp16 mma.sync.m16n8k16 (fp32 accum), fragment-permuted
// packed operands. BM=128, BN=128, BK=64, 256 thr (8 warps 2m x 4n),
// warp tile 64x32. 3-stage cp.async ring, pure contiguous copies.
// ===========================================================================

#define NTHREADS 256
#define STAGE_BYTES 32768u           // A 16KB + B 16KB (128x64 fp16 each)
#define SMEM_REQ (3 * 32768)

// ---- device scratch ----
__device__ uint32_t g_Apack0[16777216];   // 32768 x 1024 fp16 (as fp16x2 words)
__device__ uint32_t g_Apack1[16777216];
// W pack tiles: 128n x 64k fp16 = 4096 words each, [ntile][ktile]
// L1: 8nt*16kt, L2: 7*16, L3: 4*13, L4: 5*7
__device__ uint32_t g_Wpack[1339392];
#define WOFF1 0
#define WOFF2 524288
#define WOFF3 983040
#define WOFF4 1196032

// ---------------------------------------------------------------------------
__device__ __forceinline__ uint32_t smem_u32(const void* p) {
    uint32_t a;
    asm("{ .reg .u64 t; cvta.to.shared.u64 t, %1; cvt.u32.u64 %0, t; }" : "=r"(a) : "l"(p));
    return a;
}
__device__ __forceinline__ void cpa16(uint32_t saddr, const void* g) {
    asm volatile("cp.async.cg.shared.global [%0], [%1], 16;" :: "r"(saddr), "l"(g));
}
#define CPA_COMMIT() asm volatile("cp.async.commit_group;" ::: "memory")
#define CPA_WAIT1()  asm volatile("cp.async.wait_group 1;" ::: "memory")

__device__ __forceinline__ void mma_f16(float* c,
                                        uint32_t a0, uint32_t a1, uint32_t a2, uint32_t a3,
                                        uint32_t b0, uint32_t b1) {
    asm volatile("mma.sync.aligned.m16n8k16.row.col.f32.f16.f16.f32 "
                 "{%0,%1,%2,%3}, {%4,%5,%6,%7}, {%8,%9}, {%0,%1,%2,%3};"
                 : "+f"(c[0]), "+f"(c[1]), "+f"(c[2]), "+f"(c[3])
                 : "r"(a0), "r"(a1), "r"(a2), "r"(a3), "r"(b0), "r"(b1));
}

__device__ __forceinline__ uint32_t pack_half2(float lo, float hi) {
    __half2 h = __floats2half2_rn(lo, hi);
    return *(uint32_t*)&h;
}

// A-pack word index for element pair (row r, cols c..c+1), c even.
// Tile (128r x 64k) = 4096 words: [frag8*4+kk][lane32][word4]
__device__ __forceinline__ size_t wordA(int r, int c, int T) {
    int mtile = r >> 7, frag = (r >> 4) & 7, g = r & 7, half = (r >> 3) & 1;
    int kt = c >> 6, kloc = c & 63, kk = kloc >> 4, k16 = kloc & 15;
    int khi = k16 >> 3, t = (k16 >> 1) & 3;
    return (((size_t)(mtile * T + kt)) << 12)
         + (size_t)(((frag * 4 + kk) * 32 + 4 * g + t) * 4 + half + 2 * khi);
}
// W-pack word index for (n, cols c..c+1). Tile 4096 words: [nj16*4+kk][lane32][word2]
__device__ __forceinline__ size_t wordW(int n, int c, int T) {
    int ntile = n >> 7, nj = (n >> 3) & 15, g = n & 7;
    int kt = c >> 6, kloc = c & 63, kk = kloc >> 4, k16 = kloc & 15;
    int khi = k16 >> 3, t = (k16 >> 1) & 3;
    return (((size_t)(ntile * T + kt)) << 12)
         + (size_t)(((nj * 4 + kk) * 32 + 4 * g + t) * 2 + khi);
}

// ---------------------------------------------------------------------------
// Prep: pack masked weights as fp16. One fp16x2 pair per iteration.
// ---------------------------------------------------------------------------
__global__ void wpack_kernel(const float* __restrict__ W, const uint32_t* __restrict__ Msk,
                             uint32_t* __restrict__ out, int N, int K, int Kpad, int nTiles)
{
    int T = Kpad >> 6;
    int Kp2 = Kpad >> 1;
    size_t total = (size_t)nTiles * 128 * Kp2;
    for (size_t idx = (size_t)blockIdx.x * blockDim.x + threadIdx.x; idx < total;
         idx += (size_t)gridDim.x * blockDim.x) {
        int n = (int)(idx / Kp2);
        int c = (int)(idx % Kp2) * 2;
        float lo = 0.f, hi = 0.f;
        if (n < N) {
            size_t off = (size_t)n * K + c;
            if (c < K     && Msk[off]     != 0u) lo = W[off];
            if (c + 1 < K && Msk[off + 1] != 0u) hi = W[off + 1];
        }
        out[wordW(n, c, T)] = pack_half2(lo, hi);
    }
}

// Prep: pack x [32768,1024] fp32 -> fp16 pack. One float4 per thread.
__global__ void xpack_kernel(const float* __restrict__ X, uint32_t* __restrict__ out)
{
    const int K = 1024, T = 16;
    int idx = blockIdx.x * blockDim.x + threadIdx.x;
    int kc = idx & 255, r = idx >> 8;
    int k = kc * 4;
    float4 v = *(const float4*)&X[(size_t)r * K + k];
    size_t w0 = wordA(r, k, T);          // pair (k, k+1)
    out[w0]     = pack_half2(v.x, v.y);
    out[w0 + 4] = pack_half2(v.z, v.w);  // pair (k+2, k+3): t -> t+1 = +4 words
}

// ---------------------------------------------------------------------------
// Main GEMM: C = act(Apack @ Wpack^T + bias); emits fp16 pack of C.
// ---------------------------------------------------------------------------
__global__ __launch_bounds__(NTHREADS, 2)
void mma_layer_kernel(const uint32_t* __restrict__ Ap, const uint32_t* __restrict__ Wp,
                      const float* __restrict__ bias, float* __restrict__ C,
                      uint32_t* __restrict__ packOut,
                      int N, int T, int Tn, int KpadNext, int doRelu)
{
    extern __shared__ uint32_t dynsmem[];
    const uint32_t sbase = smem_u32(dynsmem);

    const int tid    = threadIdx.x;
    const int warp   = tid >> 5;
    const int lane   = tid & 31;
    const int warp_n = warp & 3;
    const int warp_m = warp >> 2;
    const int g      = lane >> 2;
    const int t      = lane & 3;
    const int mtile  = blockIdx.y;
    const int ntile  = blockIdx.x;
    const int m0     = mtile << 7;
    const int n0     = ntile << 7;

    const uint32_t* aSrc = Ap + ((size_t)mtile * T << 12);
    const uint32_t* wSrc = Wp + ((size_t)ntile * T << 12);

    float acc[4][4][4];
    #pragma unroll
    for (int i = 0; i < 4; i++)
        #pragma unroll
        for (int j = 0; j < 4; j++)
            #pragma unroll
            for (int q = 0; q < 4; q++) acc[i][j][q] = 0.f;

    auto issue = [&](int s, int kb) {
        uint32_t ab = sbase + (uint32_t)s * STAGE_BYTES;
        uint32_t wb = ab + 16384u;
        const uint32_t* a = aSrc + ((size_t)kb << 12);
        const uint32_t* w = wSrc + ((size_t)kb << 12);
        #pragma unroll
        for (int j = 0; j < 4; j++) {
            int o = tid + j * 256;
            cpa16(ab + o * 16u, a + o * 4);
            cpa16(wb + o * 16u, w + o * 4);
        }
        CPA_COMMIT();
    };

    issue(0, 0);
    if (T > 1) issue(1, 1);

    for (int kb = 0; kb < T; kb++) {
        CPA_WAIT1();
        __syncthreads();
        if (kb + 2 < T) issue((kb + 2) % 3, kb + 2);

        const int s = kb % 3;
        const uint32_t ab = sbase + (uint32_t)s * STAGE_BYTES;
        const uint32_t wb = ab + 16384u;

        #pragma unroll
        for (int kk = 0; kk < 4; kk++) {
            uint32_t a[4][4], b[4][2];
            #pragma unroll
            for (int mi = 0; mi < 4; mi++) {
                int frag = warp_m * 4 + mi;
                uint32_t addr = ab + (uint32_t)(((frag * 4 + kk) * 32 + lane) * 16);
                asm volatile("ld.shared.v4.u32 {%0,%1,%2,%3}, [%4];"
                             : "=r"(a[mi][0]), "=r"(a[mi][1]), "=r"(a[mi][2]), "=r"(a[mi][3])
                             : "r"(addr));
            }
            #pragma unroll
            for (int nj = 0; nj < 4; nj++) {
                int njg = warp_n * 4 + nj;
                uint32_t addr = wb + (uint32_t)((((njg * 4 + kk) * 32) + lane) * 8);
                asm volatile("ld.shared.v2.u32 {%0,%1}, [%2];"
                             : "=r"(b[nj][0]), "=r"(b[nj][1]) : "r"(addr));
            }
            #pragma unroll
            for (int mi = 0; mi < 4; mi++)
                #pragma unroll
                for (int nj = 0; nj < 4; nj++)
                    mma_f16(acc[mi][nj], a[mi][0], a[mi][1], a[mi][2], a[mi][3],
                            b[nj][0], b[nj][1]);
        }
        __syncthreads();
    }

    // ---- epilogue: bias + relu -> C (fp32), fp16 pack -> next layer ----
    #pragma unroll
    for (int mi = 0; mi < 4; mi++) {
        int r0 = m0 + warp_m * 64 + mi * 16 + g;
        #pragma unroll
        for (int nj = 0; nj < 4; nj++) {
            int cb = n0 + warp_n * 32 + nj * 8 + t * 2;
            float v0 = acc[mi][nj][0], v1 = acc[mi][nj][1];
            float v2 = acc[mi][nj][2], v3 = acc[mi][nj][3];
            if (cb < N) {     // N is even -> cb+1 < N too
                float b0 = bias[cb], b1 = bias[cb + 1];
                v0 += b0; v1 += b1; v2 += b0; v3 += b1;
                if (doRelu) {
                    v0 = fmaxf(v0, 0.f); v1 = fmaxf(v1, 0.f);
                    v2 = fmaxf(v2, 0.f); v3 = fmaxf(v3, 0.f);
                }
                *(float2*)&C[(size_t)r0 * N + cb]       = make_float2(v0, v1);
                *(float2*)&C[(size_t)(r0 + 8) * N + cb] = make_float2(v2, v3);
            } else { v0 = v1 = v2 = v3 = 0.f; }
            if (packOut && cb < KpadNext) {
                packOut[wordA(r0,     cb, Tn)] = pack_half2(v0, v1);
                packOut[wordA(r0 + 8, cb, Tn)] = pack_half2(v2, v3);
            }
        }
    }
}

// ---------------------------------------------------------------------------
// Layer 5: [B,600] -> [B,6] GEMV, warp per row, writes both h5 slots.
// ---------------------------------------------------------------------------
__global__ __launch_bounds__(256)
void final_layer_kernel(const float* __restrict__ A, const float* __restrict__ W,
                        const uint32_t* __restrict__ Msk, const float* __restrict__ bias,
                        float* __restrict__ O1, float* __restrict__ O2, int K)
{
    __shared__ float ws[600 * 6];
    const int tid = threadIdx.x;
    for (int idx = tid; idx < K * 6; idx += 256) {
        int n = idx / K, k = idx % K;
        size_t off = (size_t)n * K + k;
        ws[k * 6 + n] = (Msk[off] != 0u) ? W[off] : 0.0f;
    }
    __syncthreads();

    const int warp = tid >> 5, lane = tid & 31;
    const int row  = blockIdx.x * 8 + warp;
    const float* a = &A[(size_t)row * K];

    float acc[6] = {0.f, 0.f, 0.f, 0.f, 0.f, 0.f};
    for (int k = lane; k < K; k += 32) {
        float av = a[k];
        #pragma unroll
        for (int j = 0; j < 6; j++) acc[j] = fmaf(av, ws[k * 6 + j], acc[j]);
    }
    #pragma unroll
    for (int j = 0; j < 6; j++)
        #pragma unroll
        for (int o = 16; o > 0; o >>= 1)
            acc[j] += __shfl_xor_sync(0xffffffffu, acc[j], o);
    if (lane == 0) {
        #pragma unroll
        for (int j = 0; j < 6; j++) {
            float v = acc[j] + bias[j];
            O1[(size_t)row * 6 + j] = v;
            O2[(size_t)row * 6 + j] = v;
        }
    }
}

// ---------------------------------------------------------------------------
extern "C" void kernel_launch(void* const* d_in, const int* in_sizes, int n_in,
                              void* d_out, int out_size)
{
    (void)in_sizes; (void)n_in; (void)out_size;
    const int B = 32768;

    const float*    x  = (const float*)d_in[0];
    const float*    W1 = (const float*)d_in[1];
    const float*    b1 = (const float*)d_in[2];
    const uint32_t* m1 = (const uint32_t*)d_in[3];
    const float*    W2 = (const float*)d_in[4];
    const float*    b2 = (const float*)d_in[5];
    const uint32_t* m2 = (const uint32_t*)d_in[6];
    const float*    W3 = (const float*)d_in[7];
    const float*    b3 = (const float*)d_in[8];
    const uint32_t* m3 = (const uint32_t*)d_in[9];
    const float*    W4 = (const float*)d_in[10];
    const float*    b4 = (const float*)d_in[11];
    const uint32_t* m4 = (const uint32_t*)d_in[12];
    const float*    W5 = (const float*)d_in[13];
    const float*    b5 = (const float*)d_in[14];
    const uint32_t* m5 = (const uint32_t*)d_in[15];

    float* out = (float*)d_out;
    float* h5a = out;                    // [B,6]
    float* h1  = out + (size_t)B * 6;    // [B,1000]
    float* h2  = h1  + (size_t)B * 1000; // [B,800]
    float* h3  = h2  + (size_t)B * 800;  // [B,400]
    float* h4  = h3  + (size_t)B * 400;  // [B,600]
    float* h5b = h4  + (size_t)B * 600;  // [B,6]

    uint32_t *ap0, *ap1, *wp;
    cudaGetSymbolAddress((void**)&ap0, g_Apack0);
    cudaGetSymbolAddress((void**)&ap1, g_Apack1);
    cudaGetSymbolAddress((void**)&wp,  g_Wpack);

    static bool attrDone = false;
    if (!attrDone) {
        cudaFuncSetAttribute(mma_layer_kernel, cudaFuncAttributeMaxDynamicSharedMemorySize, SMEM_REQ);
        attrDone = true;
    }

    // ---- prep: pack weights (fp16, masked) + x ----
    wpack_kernel<<<512, 256>>>(W1, m1, wp + WOFF1, 1000, 1024, 1024, 8);
    wpack_kernel<<<512, 256>>>(W2, m2, wp + WOFF2,  800, 1000, 1024, 7);
    wpack_kernel<<<256, 256>>>(W3, m3, wp + WOFF3,  400,  800,  832, 4);
    wpack_kernel<<<256, 256>>>(W4, m4, wp + WOFF4,  600,  400,  448, 5);
    xpack_kernel<<<B, 256>>>(x, ap0);

    dim3 blk(NTHREADS);
    const int SM = SMEM_REQ;
    // L1: Kpad=1024 (T=16) -> h1 [B,1000]; pack -> ap1 (KpadNext=1024, Tn=16)
    mma_layer_kernel<<<dim3(8, B/128), blk, SM>>>(ap0, wp + WOFF1, b1, h1, ap1, 1000, 16, 16, 1024, 1);
    // L2: Kpad=1024 (T=16) -> h2 [B,800]; pack -> ap0 (KpadNext=832, Tn=13)
    mma_layer_kernel<<<dim3(7, B/128), blk, SM>>>(ap1, wp + WOFF2, b2, h2, ap0,  800, 16, 13,  832, 1);
    // L3: Kpad=832 (T=13) -> h3 [B,400]; pack -> ap1 (KpadNext=448, Tn=7)
    mma_layer_kernel<<<dim3(4, B/128), blk, SM>>>(ap0, wp + WOFF3, b3, h3, ap1,  400, 13,  7,  448, 1);
    // L4: Kpad=448 (T=7) -> h4 [B,600]; no pack, no relu
    mma_layer_kernel<<<dim3(5, B/128), blk, SM>>>(ap1, wp + WOFF4, b4, h4, (uint32_t*)0, 600, 7, 0, 0, 0);
    // L5 GEMV
    final_layer_kernel<<<B/8, 256>>>(h4, W5, m5, b5, h5a, h5b, 600);
}